// round 2
// baseline (speedup 1.0000x reference)
#include <cuda_runtime.h>
#include <math.h>

#define T_  1024
#define B_  128
#define D_  512
#define H_  256
#define TB_ (T_ * B_)      // 131072
#define G4_ (4 * H_)       // 1024
#define NCTA 128

// ---------------- scratch (device globals; no cudaMalloc allowed) ----------
__device__ float g_h [(size_t)TB_ * H_];    // tanh(fc) output        134 MB
__device__ float g_gx[(size_t)TB_ * G4_];   // precomputed gate inputs 537 MB
__device__ float g_hs[(size_t)TB_ * H_];    // recurrence outputs      134 MB
__device__ float g_z0[(size_t)TB_ * H_];    // classifier tmp          134 MB
__device__ float g_z1[(size_t)TB_ * H_];    // classifier tmp          134 MB
__device__ float g_Wx[G4_ * H_];            // packed input weights  (f,i,u,o)
__device__ float g_Wh[G4_ * H_];            // packed recurrent weights
__device__ float g_bias[G4_];               // packed biases
__device__ float g_hx[2 * B_ * H_];         // double-buffered hidden state
__device__ unsigned g_bar_in  = 0;          // grid barrier
__device__ unsigned g_bar_gen = 0;

// ---------------- pack gate weights: rows [f|i|u|o], split x/h halves ------
__global__ void pack_kernel(const float* __restrict__ fw, const float* __restrict__ iw,
                            const float* __restrict__ uw, const float* __restrict__ ow,
                            const float* __restrict__ fb, const float* __restrict__ ib,
                            const float* __restrict__ ub, const float* __restrict__ ob)
{
    int idx = blockIdx.x * 256 + threadIdx.x;      // 0 .. G4_*H_-1
    int row = idx >> 8;                            // 0..1023
    int k   = idx & 255;
    int gate = row >> 8;                           // 0..3
    int rl   = row & 255;
    const float* w = (gate == 0) ? fw : (gate == 1) ? iw : (gate == 2) ? uw : ow;
    g_Wx[idx] = w[rl * (2 * H_) + k];
    g_Wh[idx] = w[rl * (2 * H_) + H_ + k];
    if (idx < G4_) {
        int g2 = idx >> 8;
        const float* b = (g2 == 0) ? fb : (g2 == 1) ? ib : (g2 == 2) ? ub : ob;
        g_bias[idx] = b[idx & 255];
    }
}

// ---------------- generic fp32 GEMM:  C[M,N] = act(A[M,K] @ W[N,K]^T + bias)
#define BM 128
#define BN 64
#define BK 32

__global__ void __launch_bounds__(256) gemm_bias_act(
    const float* __restrict__ A, const float* __restrict__ W,
    const float* __restrict__ bias, float* __restrict__ C,
    int K, int N, int act)
{
    __shared__ float As[BK][BM + 4];
    __shared__ float Ws[BK][BN + 4];
    int tid = threadIdx.x;
    int m0 = blockIdx.y * BM;
    int n0 = blockIdx.x * BN;
    int tx = tid & 15;        // 16 col groups of 4
    int ty = tid >> 4;        // 16 row groups of 8
    int lr = tid >> 3;        // 0..31
    int lk = (tid & 7) << 2;  // 0..28

    float acc[8][4];
#pragma unroll
    for (int i = 0; i < 8; i++)
#pragma unroll
        for (int j = 0; j < 4; j++) acc[i][j] = 0.f;

    for (int k0 = 0; k0 < K; k0 += BK) {
#pragma unroll
        for (int i = 0; i < 4; i++) {
            int r = lr + i * 32;
            float4 v = *(const float4*)&A[(size_t)(m0 + r) * K + k0 + lk];
            As[lk + 0][r] = v.x; As[lk + 1][r] = v.y;
            As[lk + 2][r] = v.z; As[lk + 3][r] = v.w;
        }
#pragma unroll
        for (int i = 0; i < 2; i++) {
            int r = lr + i * 32;
            float4 v = *(const float4*)&W[(size_t)(n0 + r) * K + k0 + lk];
            Ws[lk + 0][r] = v.x; Ws[lk + 1][r] = v.y;
            Ws[lk + 2][r] = v.z; Ws[lk + 3][r] = v.w;
        }
        __syncthreads();
#pragma unroll
        for (int kk = 0; kk < BK; kk++) {
            float4 a0 = *(const float4*)&As[kk][ty * 8];
            float4 a1 = *(const float4*)&As[kk][ty * 8 + 4];
            float4 wv = *(const float4*)&Ws[kk][tx * 4];
            float am[8] = {a0.x, a0.y, a0.z, a0.w, a1.x, a1.y, a1.z, a1.w};
            float wm[4] = {wv.x, wv.y, wv.z, wv.w};
#pragma unroll
            for (int i = 0; i < 8; i++)
#pragma unroll
                for (int j = 0; j < 4; j++)
                    acc[i][j] = fmaf(am[i], wm[j], acc[i][j]);
        }
        __syncthreads();
    }

#pragma unroll
    for (int i = 0; i < 8; i++) {
        int row = m0 + ty * 8 + i;
        float4 o;
        float* ov = (float*)&o;
#pragma unroll
        for (int j = 0; j < 4; j++) {
            float v = acc[i][j] + bias[n0 + tx * 4 + j];
            if (act == 1) v = tanhf(v);
            else if (act == 2) v = fmaxf(v, 0.f);
            ov[j] = v;
        }
        *(float4*)&C[(size_t)row * N + n0 + tx * 4] = o;
    }
}

// ---------------- recurrence ----------------------------------------------
__device__ __forceinline__ float sigmoidf_(float x) {
    return 1.f / (1.f + expf(-x));
}

__device__ __forceinline__ void grid_barrier(unsigned* s_gen_p) {
    __syncthreads();
    if (threadIdx.x == 0) {
        unsigned my = *s_gen_p;
        __threadfence();
        unsigned t = atomicAdd(&g_bar_in, 1u);
        if (t == NCTA - 1) {
            g_bar_in = 0;
            __threadfence();
            atomicAdd(&g_bar_gen, 1u);
        } else {
            while (*(volatile unsigned*)&g_bar_gen == my) { }
        }
        *s_gen_p = my + 1;
    }
    __syncthreads();
}

// 128 CTAs: cta = bs*8 + cs. CTA owns batch rows [8*bs, 8*bs+8) and hidden
// cols [32*cs, 32*cs+32). Recurrent weights are register-resident:
// thread (r = tid&127, kh = tid>>7) owns Wh row (g*256 + cs*32 + jl),
// k-half kh (128 floats). Per step: broadcast hx from smem, FFMA, reduce
// halves + gather gates through smem, apply gating, publish hx via L2.
__global__ void __launch_bounds__(256, 1) recur_kernel()
{
    __shared__ float hx_sm[8 * 256];
    __shared__ float red[2 * 128 * 9];
    __shared__ unsigned s_gen;

    int tid = threadIdx.x;
    int cta = blockIdx.x;
    int bs = cta >> 3, cs = cta & 7;

    // ---- GEMM role ----
    int r  = tid & 127;
    int kh = tid >> 7;
    int gg = r >> 5, jl = r & 31;
    int R = gg * H_ + cs * 32 + jl;          // row in packed Wh [1024 x 256]
    float wreg[128];
    {
        const float4* wp = (const float4*)&g_Wh[(size_t)R * H_ + kh * 128];
#pragma unroll
        for (int q = 0; q < 32; q++) {
            float4 v = wp[q];
            wreg[4 * q + 0] = v.x; wreg[4 * q + 1] = v.y;
            wreg[4 * q + 2] = v.z; wreg[4 * q + 3] = v.w;
        }
    }

    // ---- gating role ----
    int b    = tid >> 5;
    int lane = tid & 31;
    int bidx = bs * 8 + b;
    int col  = cs * 32 + lane;
    float cx = 0.f;

    // zero hx buffer 0 (fresh every launch / graph replay)
    g_hx[bidx * H_ + col] = 0.f;
    if (tid == 0) s_gen = *(volatile unsigned*)&g_bar_gen;
    grid_barrier(&s_gen);

    for (int t = 0; t < T_; t++) {
        int cur = t & 1, nxt = cur ^ 1;

        // prefetch precomputed gate inputs (DRAM, independent of hx)
        const float* gxrow = &g_gx[((size_t)t * B_ + bidx) * G4_ + col];
        float gx0 = __ldg(&gxrow[0]);
        float gx1 = __ldg(&gxrow[256]);
        float gx2 = __ldg(&gxrow[512]);
        float gx3 = __ldg(&gxrow[768]);

        // load this CTA's 8 batch rows of hx (L2-coherent: bypass L1)
        {
            const float4* src = (const float4*)&g_hx[cur * (B_ * H_) + bs * 8 * H_];
            float4* dst = (float4*)hx_sm;
            dst[tid]       = __ldcg(&src[tid]);
            dst[tid + 256] = __ldcg(&src[tid + 256]);
        }
        __syncthreads();

        // hx @ Wh^T partial (this thread: 8 batch rows, one weight row-half)
        float acc[8];
#pragma unroll
        for (int bb = 0; bb < 8; bb++) acc[bb] = 0.f;
        const float* hbase = hx_sm + kh * 128;
#pragma unroll
        for (int q = 0; q < 32; q++) {
#pragma unroll
            for (int bb = 0; bb < 8; bb++) {
                float4 hv = *(const float4*)&hbase[bb * 256 + 4 * q];
                acc[bb] = fmaf(wreg[4 * q + 0], hv.x, acc[bb]);
                acc[bb] = fmaf(wreg[4 * q + 1], hv.y, acc[bb]);
                acc[bb] = fmaf(wreg[4 * q + 2], hv.z, acc[bb]);
                acc[bb] = fmaf(wreg[4 * q + 3], hv.w, acc[bb]);
            }
        }
#pragma unroll
        for (int bb = 0; bb < 8; bb++)
            red[(kh * 128 + r) * 9 + bb] = acc[bb];
        __syncthreads();

        // gather 4 gates for (bidx, col), reduce k-halves, apply gating
        float s0 = red[(0 * 32 + lane) * 9 + b] + red[(128 + 0 * 32 + lane) * 9 + b];
        float s1 = red[(1 * 32 + lane) * 9 + b] + red[(128 + 1 * 32 + lane) * 9 + b];
        float s2 = red[(2 * 32 + lane) * 9 + b] + red[(128 + 2 * 32 + lane) * 9 + b];
        float s3 = red[(3 * 32 + lane) * 9 + b] + red[(128 + 3 * 32 + lane) * 9 + b];

        float fg = sigmoidf_(s0 + gx0);
        float ig = sigmoidf_(s1 + gx1);
        float ug = tanhf(s2 + gx2);
        float og = sigmoidf_(s3 + gx3);
        cx = fg * cx + ig * ug;
        float h = og * tanhf(cx);

        g_hx[nxt * (B_ * H_) + bidx * H_ + col] = h;
        g_hs[((size_t)t * B_ + bidx) * H_ + col] = h;

        grid_barrier(&s_gen);
    }
}

// ---------------- final tiny projection to 2 logits ------------------------
__global__ void __launch_bounds__(256) final_kernel(
    const float* __restrict__ z, const float* __restrict__ w2,
    const float* __restrict__ b2, float* __restrict__ out)
{
    __shared__ float w[512];
    __shared__ float bb[2];
    int tid = threadIdx.x;
    w[tid] = w2[tid];
    w[tid + 256] = w2[tid + 256];
    if (tid < 2) bb[tid] = b2[tid];
    __syncthreads();

    int row = blockIdx.x * 256 + tid;
    const float4* zp = (const float4*)&z[(size_t)row * H_];
    float a0 = 0.f, a1 = 0.f;
#pragma unroll
    for (int q = 0; q < 64; q++) {
        float4 v = zp[q];
        a0 = fmaf(v.x, w[4 * q + 0], a0);
        a0 = fmaf(v.y, w[4 * q + 1], a0);
        a0 = fmaf(v.z, w[4 * q + 2], a0);
        a0 = fmaf(v.w, w[4 * q + 3], a0);
        a1 = fmaf(v.x, w[256 + 4 * q + 0], a1);
        a1 = fmaf(v.y, w[256 + 4 * q + 1], a1);
        a1 = fmaf(v.z, w[256 + 4 * q + 2], a1);
        a1 = fmaf(v.w, w[256 + 4 * q + 3], a1);
    }
    out[row * 2 + 0] = a0 + bb[0];
    out[row * 2 + 1] = a1 + bb[1];
}

// ---------------- host -----------------------------------------------------
extern "C" void kernel_launch(void* const* d_in, const int* in_sizes, int n_in,
                              void* d_out, int out_size)
{
    const float* x    = (const float*)d_in[0];
    const float* fc_w = (const float*)d_in[1];
    const float* fc_b = (const float*)d_in[2];
    const float* fw   = (const float*)d_in[3];
    const float* fb   = (const float*)d_in[4];
    const float* iw   = (const float*)d_in[5];
    const float* ib   = (const float*)d_in[6];
    const float* uw   = (const float*)d_in[7];
    const float* ub   = (const float*)d_in[8];
    const float* ow   = (const float*)d_in[9];
    const float* ob   = (const float*)d_in[10];
    const float* w0   = (const float*)d_in[11];
    const float* b0   = (const float*)d_in[12];
    const float* w1   = (const float*)d_in[13];
    const float* b1   = (const float*)d_in[14];
    const float* w2   = (const float*)d_in[15];
    const float* b2   = (const float*)d_in[16];
    float* out = (float*)d_out;

    void *p_h, *p_gx, *p_hs, *p_z0, *p_z1, *p_wx, *p_bias;
    cudaGetSymbolAddress(&p_h,    g_h);
    cudaGetSymbolAddress(&p_gx,   g_gx);
    cudaGetSymbolAddress(&p_hs,   g_hs);
    cudaGetSymbolAddress(&p_z0,   g_z0);
    cudaGetSymbolAddress(&p_z1,   g_z1);
    cudaGetSymbolAddress(&p_wx,   g_Wx);
    cudaGetSymbolAddress(&p_bias, g_bias);

    // pack gate weights / biases
    pack_kernel<<<(G4_ * H_) / 256, 256>>>(fw, iw, uw, ow, fb, ib, ub, ob);

    // h = tanh(x @ fc_w^T + fc_b)        [TB, 512] -> [TB, 256]
    gemm_bias_act<<<dim3(H_ / BN, TB_ / BM), 256>>>(
        x, fc_w, fc_b, (float*)p_h, D_, H_, 1);

    // gx = h @ Wx^T + bias               [TB, 256] -> [TB, 1024]
    gemm_bias_act<<<dim3(G4_ / BN, TB_ / BM), 256>>>(
        (const float*)p_h, (const float*)p_wx, (const float*)p_bias,
        (float*)p_gx, H_, G4_, 0);

    // LSTM recurrence (persistent, grid-barrier synchronized)
    recur_kernel<<<NCTA, 256>>>();

    // classifier
    gemm_bias_act<<<dim3(H_ / BN, TB_ / BM), 256>>>(
        (const float*)p_hs, w0, b0, (float*)p_z0, H_, H_, 2);
    gemm_bias_act<<<dim3(H_ / BN, TB_ / BM), 256>>>(
        (const float*)p_z0, w1, b1, (float*)p_z1, H_, H_, 2);
    final_kernel<<<TB_ / 256, 256>>>((const float*)p_z1, w2, b2, out);
}

// round 4
// speedup vs baseline: 1.2424x; 1.2424x over previous
#include <cuda_runtime.h>
#include <cuda_bf16.h>
#include <math.h>
#include <stdint.h>

#define T_  1024
#define B_  128
#define D_  512
#define H_  256
#define TB_ (T_ * B_)      // 131072
#define G4_ (4 * H_)       // 1024
#define NCTA 128

// ---------------- scratch (device globals; no cudaMalloc allowed) ----------
__device__ float g_h [(size_t)TB_ * H_];    // tanh(fc) output
__device__ float g_gx[(size_t)TB_ * G4_];   // precomputed gate inputs
__device__ float g_hs[(size_t)TB_ * H_];    // recurrence outputs
__device__ float g_z0[(size_t)TB_ * H_];    // classifier tmp
__device__ float g_z1[(size_t)TB_ * H_];    // classifier tmp
__device__ float g_Wx[G4_ * H_];            // packed input weights (f,i,u,o)
__device__ float g_Wh[G4_ * H_];            // packed recurrent weights
__device__ float g_bias[G4_];               // packed biases
__device__ float g_hx[2 * B_ * H_];         // double-buffered hidden state
__device__ unsigned g_bar_in  = 0;          // grid barrier
__device__ unsigned g_bar_gen = 0;

// ================= helpers ==================================================
__device__ __forceinline__ uint32_t smem_u32(const void* p) {
    uint32_t a;
    asm("{ .reg .u64 t; cvta.to.shared.u64 t, %1; cvt.u32.u64 %0, t; }"
        : "=r"(a) : "l"(p));
    return a;
}

__device__ __forceinline__ void mma_bf16(float* c, const uint32_t* a,
                                         const uint32_t* b) {
    asm volatile(
        "mma.sync.aligned.m16n8k16.row.col.f32.bf16.bf16.f32 "
        "{%0,%1,%2,%3}, {%4,%5,%6,%7}, {%8,%9}, {%0,%1,%2,%3};"
        : "+f"(c[0]), "+f"(c[1]), "+f"(c[2]), "+f"(c[3])
        : "r"(a[0]), "r"(a[1]), "r"(a[2]), "r"(a[3]), "r"(b[0]), "r"(b[1]));
}

__device__ __forceinline__ void ldsm4(uint32_t* d, uint32_t addr) {
    asm volatile("ldmatrix.sync.aligned.m8n8.x4.shared.b16 {%0,%1,%2,%3}, [%4];"
        : "=r"(d[0]), "=r"(d[1]), "=r"(d[2]), "=r"(d[3]) : "r"(addr));
}

__device__ __forceinline__ uint32_t pack2(__nv_bfloat16 a, __nv_bfloat16 b) {
    __nv_bfloat162 p = __halves2bfloat162(a, b);
    return *reinterpret_cast<uint32_t*>(&p);
}

// split float4 into bf16 hi-pair and lo-pair (bf16x3 scheme)
__device__ __forceinline__ void split4(float4 v, uint2& hi, uint2& lo) {
    __nv_bfloat16 hx = __float2bfloat16_rn(v.x);
    __nv_bfloat16 hy = __float2bfloat16_rn(v.y);
    __nv_bfloat16 hz = __float2bfloat16_rn(v.z);
    __nv_bfloat16 hw = __float2bfloat16_rn(v.w);
    __nv_bfloat16 lx = __float2bfloat16_rn(v.x - __bfloat162float(hx));
    __nv_bfloat16 ly = __float2bfloat16_rn(v.y - __bfloat162float(hy));
    __nv_bfloat16 lz = __float2bfloat16_rn(v.z - __bfloat162float(hz));
    __nv_bfloat16 lw = __float2bfloat16_rn(v.w - __bfloat162float(hw));
    hi.x = pack2(hx, hy); hi.y = pack2(hz, hw);
    lo.x = pack2(lx, ly); lo.y = pack2(lz, lw);
}

// ---------------- pack gate weights: rows [f|i|u|o], split x/h halves ------
__global__ void pack_kernel(const float* __restrict__ fw, const float* __restrict__ iw,
                            const float* __restrict__ uw, const float* __restrict__ ow,
                            const float* __restrict__ fb, const float* __restrict__ ib,
                            const float* __restrict__ ub, const float* __restrict__ ob)
{
    int idx = blockIdx.x * 256 + threadIdx.x;
    int row = idx >> 8;
    int k   = idx & 255;
    int gate = row >> 8;
    int rl   = row & 255;
    const float* w = (gate == 0) ? fw : (gate == 1) ? iw : (gate == 2) ? uw : ow;
    g_Wx[idx] = w[rl * (2 * H_) + k];
    g_Wh[idx] = w[rl * (2 * H_) + H_ + k];
    if (idx < G4_) {
        int g2 = idx >> 8;
        const float* b = (g2 == 0) ? fb : (g2 == 1) ? ib : (g2 == 2) ? ub : ob;
        g_bias[idx] = b[idx & 255];
    }
}

// ================= bf16x3 mma.sync GEMM =====================================
// C[M,N] = act(A[M,K] @ W[N,K]^T + bias). CTA tile 128x128, 256 thr (8 warps,
// warp tile 32x64). K-chunk 32. smem per stage: A[128][64]bf16 (hi|lo) 16KB +
// B same 16KB = 32KB; double buffered = 64KB. XOR-16B swizzle per row.
#define STAGE_BYTES 32768
#define B_OFF 16384

__global__ void __launch_bounds__(256, 1) gemm_mma(
    const float* __restrict__ A, const float* __restrict__ W,
    const float* __restrict__ bias, float* __restrict__ C,
    int K, int N, int act)
{
    extern __shared__ char smc[];
    uint32_t sbase = smem_u32(smc);
    int tid = threadIdx.x, lane = tid & 31, wid = tid >> 5;
    int m0 = blockIdx.y * 128, n0 = blockIdx.x * 128;
    int wm = (wid >> 1) * 32, wn = (wid & 1) * 64;

    // lane decode for ldmatrix addressing
    int q = lane >> 3, r = lane & 7;
    int rA0 = wm + (q & 1) * 8 + r;          // A frag rows (mt adds 16)
    int cuA = q >> 1;                        // A k-unit offset (0/1)
    int rBb = wn + (q >> 1) * 8 + r;         // B frag rows (nt adds 16)
    int cuB = q & 1;                         // B k-unit offset (0/1)

    // global load mapping: 2 threads per row, 16 cols each (4 float4)
    int lrow = tid >> 1, lseg = (tid & 1) * 16;
    const float* Ag = A + (size_t)(m0 + lrow) * K + lseg;
    const float* Wg = W + (size_t)(n0 + lrow) * K + lseg;
    // smem store offsets (within stage) for the 4 float4s: hi + lo
    uint32_t sh[4], sl[4];
#pragma unroll
    for (int j = 0; j < 4; j++) {
        int col = lseg + 4 * j;
        int unit = col >> 3;
        int off = (col & 4) * 2;
        sh[j] = lrow * 128 + (((unit    ) ^ (lrow & 7)) << 4) + off;
        sl[j] = lrow * 128 + (((unit + 4) ^ (lrow & 7)) << 4) + off;
    }

    float c[2][8][4];
#pragma unroll
    for (int mt = 0; mt < 2; mt++)
#pragma unroll
        for (int f = 0; f < 8; f++)
#pragma unroll
            for (int e = 0; e < 4; e++) c[mt][f][e] = 0.f;

    int nc = K >> 5;

    // prologue: chunk 0 -> stage 0
    {
        char* st = smc;
#pragma unroll
        for (int j = 0; j < 4; j++) {
            uint2 hi, lo;
            split4(*(const float4*)&Ag[4 * j], hi, lo);
            *(uint2*)(st + sh[j]) = hi;
            *(uint2*)(st + sl[j]) = lo;
            split4(*(const float4*)&Wg[4 * j], hi, lo);
            *(uint2*)(st + B_OFF + sh[j]) = hi;
            *(uint2*)(st + B_OFF + sl[j]) = lo;
        }
    }
    __syncthreads();

#pragma unroll 1
    for (int ch = 0; ch < nc; ch++) {
        // prefetch next chunk into registers (hidden under compute)
        float4 va[4], vw[4];
        if (ch + 1 < nc) {
            const float* Ap = Ag + (ch + 1) * 32;
            const float* Wp = Wg + (ch + 1) * 32;
#pragma unroll
            for (int j = 0; j < 4; j++) {
                va[j] = *(const float4*)&Ap[4 * j];
                vw[j] = *(const float4*)&Wp[4 * j];
            }
        }

        uint32_t st = sbase + (ch & 1) * STAGE_BYTES;
#pragma unroll
        for (int kk = 0; kk < 2; kk++) {
            uint32_t ah[2][4], al[2][4], bh[8][2], bl[8][2];
#pragma unroll
            for (int mt = 0; mt < 2; mt++) {
                int row = rA0 + mt * 16;
                ldsm4(ah[mt], st + row * 128 + (((cuA + kk * 2    ) ^ (row & 7)) << 4));
                ldsm4(al[mt], st + row * 128 + (((cuA + kk * 2 + 4) ^ (row & 7)) << 4));
            }
#pragma unroll
            for (int nt = 0; nt < 4; nt++) {
                int row = rBb + nt * 16;
                uint32_t t4[4];
                ldsm4(t4, st + B_OFF + row * 128 + (((cuB + kk * 2    ) ^ (row & 7)) << 4));
                bh[nt * 2][0] = t4[0]; bh[nt * 2][1] = t4[1];
                bh[nt * 2 + 1][0] = t4[2]; bh[nt * 2 + 1][1] = t4[3];
                ldsm4(t4, st + B_OFF + row * 128 + (((cuB + kk * 2 + 4) ^ (row & 7)) << 4));
                bl[nt * 2][0] = t4[0]; bl[nt * 2][1] = t4[1];
                bl[nt * 2 + 1][0] = t4[2]; bl[nt * 2 + 1][1] = t4[3];
            }
#pragma unroll
            for (int mt = 0; mt < 2; mt++)
#pragma unroll
                for (int f = 0; f < 8; f++) {
                    mma_bf16(c[mt][f], ah[mt], bh[f]);
                    mma_bf16(c[mt][f], ah[mt], bl[f]);
                    mma_bf16(c[mt][f], al[mt], bh[f]);
                }
        }

        if (ch + 1 < nc) {
            char* stw = smc + ((ch + 1) & 1) * STAGE_BYTES;
#pragma unroll
            for (int j = 0; j < 4; j++) {
                uint2 hi, lo;
                split4(va[j], hi, lo);
                *(uint2*)(stw + sh[j]) = hi;
                *(uint2*)(stw + sl[j]) = lo;
                split4(vw[j], hi, lo);
                *(uint2*)(stw + B_OFF + sh[j]) = hi;
                *(uint2*)(stw + B_OFF + sl[j]) = lo;
            }
            __syncthreads();
        }
    }

    // epilogue: bias + activation straight from fragments
#pragma unroll
    for (int mt = 0; mt < 2; mt++) {
        int row = m0 + wm + mt * 16 + (lane >> 2);
#pragma unroll
        for (int f = 0; f < 8; f++) {
            int col = n0 + wn + f * 8 + (lane & 3) * 2;
            float b0 = __ldg(&bias[col]), b1 = __ldg(&bias[col + 1]);
            float v0 = c[mt][f][0] + b0, v1 = c[mt][f][1] + b1;
            float v2 = c[mt][f][2] + b0, v3 = c[mt][f][3] + b1;
            if (act == 1) {
                v0 = tanhf(v0); v1 = tanhf(v1); v2 = tanhf(v2); v3 = tanhf(v3);
            } else if (act == 2) {
                v0 = fmaxf(v0, 0.f); v1 = fmaxf(v1, 0.f);
                v2 = fmaxf(v2, 0.f); v3 = fmaxf(v3, 0.f);
            }
            float2 o01 = make_float2(v0, v1);
            float2 o23 = make_float2(v2, v3);
            *(float2*)&C[(size_t)row * N + col] = o01;
            *(float2*)&C[(size_t)(row + 8) * N + col] = o23;
        }
    }
}

// ---------------- recurrence (unchanged from passing round) -----------------
__device__ __forceinline__ float sigmoidf_(float x) {
    return 1.f / (1.f + expf(-x));
}

__device__ __forceinline__ void grid_barrier(unsigned* s_gen_p) {
    __syncthreads();
    if (threadIdx.x == 0) {
        unsigned my = *s_gen_p;
        __threadfence();
        unsigned t = atomicAdd(&g_bar_in, 1u);
        if (t == NCTA - 1) {
            g_bar_in = 0;
            __threadfence();
            atomicAdd(&g_bar_gen, 1u);
        } else {
            while (*(volatile unsigned*)&g_bar_gen == my) { }
        }
        *s_gen_p = my + 1;
    }
    __syncthreads();
}

__global__ void __launch_bounds__(256, 1) recur_kernel()
{
    __shared__ float hx_sm[8 * 256];
    __shared__ float red[2 * 128 * 9];
    __shared__ unsigned s_gen;

    int tid = threadIdx.x;
    int cta = blockIdx.x;
    int bs = cta >> 3, cs = cta & 7;

    int r  = tid & 127;
    int kh = tid >> 7;
    int gg = r >> 5, jl = r & 31;
    int R = gg * H_ + cs * 32 + jl;
    float wreg[128];
    {
        const float4* wp = (const float4*)&g_Wh[(size_t)R * H_ + kh * 128];
#pragma unroll
        for (int q = 0; q < 32; q++) {
            float4 v = wp[q];
            wreg[4 * q + 0] = v.x; wreg[4 * q + 1] = v.y;
            wreg[4 * q + 2] = v.z; wreg[4 * q + 3] = v.w;
        }
    }

    int b    = tid >> 5;
    int lane = tid & 31;
    int bidx = bs * 8 + b;
    int col  = cs * 32 + lane;
    float cx = 0.f;

    g_hx[bidx * H_ + col] = 0.f;
    if (tid == 0) s_gen = *(volatile unsigned*)&g_bar_gen;
    grid_barrier(&s_gen);

    for (int t = 0; t < T_; t++) {
        int cur = t & 1, nxt = cur ^ 1;

        const float* gxrow = &g_gx[((size_t)t * B_ + bidx) * G4_ + col];
        float gx0 = __ldg(&gxrow[0]);
        float gx1 = __ldg(&gxrow[256]);
        float gx2 = __ldg(&gxrow[512]);
        float gx3 = __ldg(&gxrow[768]);

        {
            const float4* src = (const float4*)&g_hx[cur * (B_ * H_) + bs * 8 * H_];
            float4* dst = (float4*)hx_sm;
            dst[tid]       = __ldcg(&src[tid]);
            dst[tid + 256] = __ldcg(&src[tid + 256]);
        }
        __syncthreads();

        float acc[8];
#pragma unroll
        for (int bb = 0; bb < 8; bb++) acc[bb] = 0.f;
        const float* hbase = hx_sm + kh * 128;
#pragma unroll
        for (int q = 0; q < 32; q++) {
#pragma unroll
            for (int bb = 0; bb < 8; bb++) {
                float4 hv = *(const float4*)&hbase[bb * 256 + 4 * q];
                acc[bb] = fmaf(wreg[4 * q + 0], hv.x, acc[bb]);
                acc[bb] = fmaf(wreg[4 * q + 1], hv.y, acc[bb]);
                acc[bb] = fmaf(wreg[4 * q + 2], hv.z, acc[bb]);
                acc[bb] = fmaf(wreg[4 * q + 3], hv.w, acc[bb]);
            }
        }
#pragma unroll
        for (int bb = 0; bb < 8; bb++)
            red[(kh * 128 + r) * 9 + bb] = acc[bb];
        __syncthreads();

        float s0 = red[(0 * 32 + lane) * 9 + b] + red[(128 + 0 * 32 + lane) * 9 + b];
        float s1 = red[(1 * 32 + lane) * 9 + b] + red[(128 + 1 * 32 + lane) * 9 + b];
        float s2 = red[(2 * 32 + lane) * 9 + b] + red[(128 + 2 * 32 + lane) * 9 + b];
        float s3 = red[(3 * 32 + lane) * 9 + b] + red[(128 + 3 * 32 + lane) * 9 + b];

        float fg = sigmoidf_(s0 + gx0);
        float ig = sigmoidf_(s1 + gx1);
        float ug = tanhf(s2 + gx2);
        float og = sigmoidf_(s3 + gx3);
        cx = fg * cx + ig * ug;
        float h = og * tanhf(cx);

        g_hx[nxt * (B_ * H_) + bidx * H_ + col] = h;
        g_hs[((size_t)t * B_ + bidx) * H_ + col] = h;

        grid_barrier(&s_gen);
    }
}

// ---------------- final tiny projection to 2 logits ------------------------
__global__ void __launch_bounds__(256) final_kernel(
    const float* __restrict__ z, const float* __restrict__ w2,
    const float* __restrict__ b2, float* __restrict__ out)
{
    __shared__ float w[512];
    __shared__ float bb[2];
    int tid = threadIdx.x;
    w[tid] = w2[tid];
    w[tid + 256] = w2[tid + 256];
    if (tid < 2) bb[tid] = b2[tid];
    __syncthreads();

    int row = blockIdx.x * 256 + tid;
    const float4* zp = (const float4*)&z[(size_t)row * H_];
    float a0 = 0.f, a1 = 0.f;
#pragma unroll
    for (int q = 0; q < 64; q++) {
        float4 v = zp[q];
        a0 = fmaf(v.x, w[4 * q + 0], a0);
        a0 = fmaf(v.y, w[4 * q + 1], a0);
        a0 = fmaf(v.z, w[4 * q + 2], a0);
        a0 = fmaf(v.w, w[4 * q + 3], a0);
        a1 = fmaf(v.x, w[256 + 4 * q + 0], a1);
        a1 = fmaf(v.y, w[256 + 4 * q + 1], a1);
        a1 = fmaf(v.z, w[256 + 4 * q + 2], a1);
        a1 = fmaf(v.w, w[256 + 4 * q + 3], a1);
    }
    out[row * 2 + 0] = a0 + bb[0];
    out[row * 2 + 1] = a1 + bb[1];
}

// ---------------- host -----------------------------------------------------
extern "C" void kernel_launch(void* const* d_in, const int* in_sizes, int n_in,
                              void* d_out, int out_size)
{
    const float* x    = (const float*)d_in[0];
    const float* fc_w = (const float*)d_in[1];
    const float* fc_b = (const float*)d_in[2];
    const float* fw   = (const float*)d_in[3];
    const float* fb   = (const float*)d_in[4];
    const float* iw   = (const float*)d_in[5];
    const float* ib   = (const float*)d_in[6];
    const float* uw   = (const float*)d_in[7];
    const float* ub   = (const float*)d_in[8];
    const float* ow   = (const float*)d_in[9];
    const float* ob   = (const float*)d_in[10];
    const float* w0   = (const float*)d_in[11];
    const float* b0   = (const float*)d_in[12];
    const float* w1   = (const float*)d_in[13];
    const float* b1   = (const float*)d_in[14];
    const float* w2   = (const float*)d_in[15];
    const float* b2   = (const float*)d_in[16];
    float* out = (float*)d_out;

    void *p_h, *p_gx, *p_hs, *p_z0, *p_z1, *p_wx, *p_bias;
    cudaGetSymbolAddress(&p_h,    g_h);
    cudaGetSymbolAddress(&p_gx,   g_gx);
    cudaGetSymbolAddress(&p_hs,   g_hs);
    cudaGetSymbolAddress(&p_z0,   g_z0);
    cudaGetSymbolAddress(&p_z1,   g_z1);
    cudaGetSymbolAddress(&p_wx,   g_Wx);
    cudaGetSymbolAddress(&p_bias, g_bias);

    cudaFuncSetAttribute(gemm_mma, cudaFuncAttributeMaxDynamicSharedMemorySize,
                         2 * STAGE_BYTES);

    // pack gate weights / biases
    pack_kernel<<<(G4_ * H_) / 256, 256>>>(fw, iw, uw, ow, fb, ib, ub, ob);

    // h = tanh(x @ fc_w^T + fc_b)        [TB,512] -> [TB,256]
    gemm_mma<<<dim3(H_ / 128, TB_ / 128), 256, 2 * STAGE_BYTES>>>(
        x, fc_w, fc_b, (float*)p_h, D_, H_, 1);

    // gx = h @ Wx^T + bias               [TB,256] -> [TB,1024]
    gemm_mma<<<dim3(G4_ / 128, TB_ / 128), 256, 2 * STAGE_BYTES>>>(
        (const float*)p_h, (const float*)p_wx, (const float*)p_bias,
        (float*)p_gx, H_, G4_, 0);

    // LSTM recurrence (persistent, grid-barrier synchronized)
    recur_kernel<<<NCTA, 256>>>();

    // classifier
    gemm_mma<<<dim3(H_ / 128, TB_ / 128), 256, 2 * STAGE_BYTES>>>(
        (const float*)p_hs, w0, b0, (float*)p_z0, H_, H_, 2);
    gemm_mma<<<dim3(H_ / 128, TB_ / 128), 256, 2 * STAGE_BYTES>>>(
        (const float*)p_z0, w1, b1, (float*)p_z1, H_, H_, 2);
    final_kernel<<<TB_ / 256, 256>>>((const float*)p_z1, w2, b2, out);
}

// round 5
// speedup vs baseline: 1.2622x; 1.0159x over previous
#include <cuda_runtime.h>
#include <cuda_bf16.h>
#include <math.h>
#include <stdint.h>

#define T_  1024
#define B_  128
#define D_  512
#define H_  256
#define TB_ (T_ * B_)      // 131072
#define G4_ (4 * H_)       // 1024
#define NCTA 128

// ---------------- scratch (device globals; no cudaMalloc allowed) ----------
__device__ uint32_t g_xp [(size_t)TB_ * D_];   // x split-packed (hi<<16|lo)
__device__ uint32_t g_hb [(size_t)TB_ * H_];   // tanh(fc) packed
__device__ float    g_gx [(size_t)TB_ * G4_];  // gate inputs (f32, recur reads)
__device__ uint32_t g_hsb[(size_t)TB_ * H_];   // recurrence out packed
__device__ uint32_t g_z0b[(size_t)TB_ * H_];   // classifier tmp packed
__device__ float    g_z1 [(size_t)TB_ * H_];   // classifier tmp f32
__device__ uint32_t g_Wxp[G4_ * H_];           // packed input weights (f,i,u,o)
__device__ float    g_Wh [G4_ * H_];           // recurrent weights f32
__device__ float    g_bias[G4_];               // packed biases
__device__ uint32_t g_fcwp[H_ * D_];
__device__ uint32_t g_w0p[H_ * H_];
__device__ uint32_t g_w1p[H_ * H_];
__device__ float    g_hx[2 * B_ * H_];         // double-buffered hidden state
__device__ unsigned g_bar_in  = 0;
__device__ unsigned g_bar_gen = 0;

// ================= helpers ==================================================
__device__ __forceinline__ uint32_t smem_u32(const void* p) {
    uint32_t a;
    asm("{ .reg .u64 t; cvta.to.shared.u64 t, %1; cvt.u32.u64 %0, t; }"
        : "=r"(a) : "l"(p));
    return a;
}

__device__ __forceinline__ void mma_bf16(float* c, const uint32_t* a,
                                         const uint32_t* b) {
    asm volatile(
        "mma.sync.aligned.m16n8k16.row.col.f32.bf16.bf16.f32 "
        "{%0,%1,%2,%3}, {%4,%5,%6,%7}, {%8,%9}, {%0,%1,%2,%3};"
        : "+f"(c[0]), "+f"(c[1]), "+f"(c[2]), "+f"(c[3])
        : "r"(a[0]), "r"(a[1]), "r"(a[2]), "r"(a[3]), "r"(b[0]), "r"(b[1]));
}

__device__ __forceinline__ void ldsm4(uint32_t* d, uint32_t addr) {
    asm volatile("ldmatrix.sync.aligned.m8n8.x4.shared.b16 {%0,%1,%2,%3}, [%4];"
        : "=r"(d[0]), "=r"(d[1]), "=r"(d[2]), "=r"(d[3]) : "r"(addr));
}

// split-pack one float: (bf16_hi << 16) | bf16_lo
__device__ __forceinline__ uint32_t pk(float v) {
    __nv_bfloat16 h = __float2bfloat16_rn(v);
    float hf = __bfloat162float(h);
    __nv_bfloat16 l = __float2bfloat16_rn(v - hf);
    return ((uint32_t)__bfloat16_as_ushort(h) << 16) | __bfloat16_as_ushort(l);
}

// packed dual fp32 FMA (SASS FFMA2): d.lo += a.lo*b.lo, d.hi += a.hi*b.hi
__device__ __forceinline__ void fma2(unsigned long long& d,
                                     unsigned long long a,
                                     unsigned long long b) {
    asm("fma.rn.f32x2 %0, %1, %2, %0;" : "+l"(d) : "l"(a), "l"(b));
}

// ---------------- generic f32 -> packed splitter ---------------------------
__global__ void splitpack_kernel(const float* __restrict__ s,
                                 uint32_t* __restrict__ d, int n4) {
    int i = blockIdx.x * 256 + threadIdx.x;
    if (i < n4) {
        float4 v = ((const float4*)s)[i];
        uint4 o;
        o.x = pk(v.x); o.y = pk(v.y); o.z = pk(v.z); o.w = pk(v.w);
        ((uint4*)d)[i] = o;
    }
}

// ---------------- pack gate weights: rows [f|i|u|o], split x/h halves ------
__global__ void pack_kernel(const float* __restrict__ fw, const float* __restrict__ iw,
                            const float* __restrict__ uw, const float* __restrict__ ow,
                            const float* __restrict__ fb, const float* __restrict__ ib,
                            const float* __restrict__ ub, const float* __restrict__ ob)
{
    int idx = blockIdx.x * 256 + threadIdx.x;
    int row = idx >> 8;
    int k   = idx & 255;
    int gate = row >> 8;
    int rl   = row & 255;
    const float* w = (gate == 0) ? fw : (gate == 1) ? iw : (gate == 2) ? uw : ow;
    g_Wxp[idx] = pk(w[rl * (2 * H_) + k]);
    g_Wh[idx]  = w[rl * (2 * H_) + H_ + k];
    if (idx < G4_) {
        int g2 = idx >> 8;
        const float* b = (g2 == 0) ? fb : (g2 == 1) ? ib : (g2 == 2) ? ub : ob;
        g_bias[idx] = b[idx & 255];
    }
}

// ================= bf16x3 mma.sync GEMM (pre-split operands) ================
// C[M,N] = act(A[M,K] @ W[N,K]^T + bias). A/W are u32 packed (hi<<16|lo).
// CTA tile 128x128, 256 thr (8 warps, warp tile 32x64). K-chunk 32.
// smem per stage: A hi|lo 16KB + B hi|lo 16KB; double buffered = 64KB.
#define STAGE_BYTES 32768
#define B_OFF 16384

__global__ void __launch_bounds__(256, 1) gemm_mma(
    const uint32_t* __restrict__ A, const uint32_t* __restrict__ W,
    const float* __restrict__ bias, void* __restrict__ Cv,
    int K, int N, int act, int outpk)
{
    extern __shared__ char smc[];
    uint32_t sbase = smem_u32(smc);
    int tid = threadIdx.x, lane = tid & 31, wid = tid >> 5;
    int m0 = blockIdx.y * 128, n0 = blockIdx.x * 128;
    int wm = (wid >> 1) * 32, wn = (wid & 1) * 64;

    // lane decode for ldmatrix addressing
    int q = lane >> 3, r = lane & 7;
    int rA0 = wm + (q & 1) * 8 + r;
    int cuA = q >> 1;
    int rBb = wn + (q >> 1) * 8 + r;
    int cuB = q & 1;

    // global load mapping: 2 threads per row, 16 elems each (4 uint4)
    int lrow = tid >> 1, lseg = (tid & 1) * 16;
    const uint32_t* Ag = A + (size_t)(m0 + lrow) * K + lseg;
    const uint32_t* Wg = W + (size_t)(n0 + lrow) * K + lseg;
    uint32_t sh[4], sl[4];
#pragma unroll
    for (int j = 0; j < 4; j++) {
        int col = lseg + 4 * j;
        int unit = col >> 3;
        int off = (col & 4) * 2;
        sh[j] = lrow * 128 + (((unit    ) ^ (lrow & 7)) << 4) + off;
        sl[j] = lrow * 128 + (((unit + 4) ^ (lrow & 7)) << 4) + off;
    }

    float c[2][8][4];
#pragma unroll
    for (int mt = 0; mt < 2; mt++)
#pragma unroll
        for (int f = 0; f < 8; f++)
#pragma unroll
            for (int e = 0; e < 4; e++) c[mt][f][e] = 0.f;

    int nc = K >> 5;

    // prologue: chunk 0 -> stage 0
    {
        char* st = smc;
#pragma unroll
        for (int j = 0; j < 4; j++) {
            uint4 v = *(const uint4*)&Ag[4 * j];
            uint2 hi, lo;
            hi.x = __byte_perm(v.x, v.y, 0x7632);
            lo.x = __byte_perm(v.x, v.y, 0x5410);
            hi.y = __byte_perm(v.z, v.w, 0x7632);
            lo.y = __byte_perm(v.z, v.w, 0x5410);
            *(uint2*)(st + sh[j]) = hi;
            *(uint2*)(st + sl[j]) = lo;
            v = *(const uint4*)&Wg[4 * j];
            hi.x = __byte_perm(v.x, v.y, 0x7632);
            lo.x = __byte_perm(v.x, v.y, 0x5410);
            hi.y = __byte_perm(v.z, v.w, 0x7632);
            lo.y = __byte_perm(v.z, v.w, 0x5410);
            *(uint2*)(st + B_OFF + sh[j]) = hi;
            *(uint2*)(st + B_OFF + sl[j]) = lo;
        }
    }
    __syncthreads();

#pragma unroll 1
    for (int ch = 0; ch < nc; ch++) {
        // prefetch next chunk into registers
        uint4 va[4], vw[4];
        if (ch + 1 < nc) {
            const uint32_t* Ap = Ag + (ch + 1) * 32;
            const uint32_t* Wp = Wg + (ch + 1) * 32;
#pragma unroll
            for (int j = 0; j < 4; j++) {
                va[j] = *(const uint4*)&Ap[4 * j];
                vw[j] = *(const uint4*)&Wp[4 * j];
            }
        }

        uint32_t st = sbase + (ch & 1) * STAGE_BYTES;
#pragma unroll
        for (int kk = 0; kk < 2; kk++) {
            uint32_t ah[2][4], al[2][4], bh[8][2], bl[8][2];
#pragma unroll
            for (int mt = 0; mt < 2; mt++) {
                int row = rA0 + mt * 16;
                ldsm4(ah[mt], st + row * 128 + (((cuA + kk * 2    ) ^ (row & 7)) << 4));
                ldsm4(al[mt], st + row * 128 + (((cuA + kk * 2 + 4) ^ (row & 7)) << 4));
            }
#pragma unroll
            for (int nt = 0; nt < 4; nt++) {
                int row = rBb + nt * 16;
                uint32_t t4[4];
                ldsm4(t4, st + B_OFF + row * 128 + (((cuB + kk * 2    ) ^ (row & 7)) << 4));
                bh[nt * 2][0] = t4[0]; bh[nt * 2][1] = t4[1];
                bh[nt * 2 + 1][0] = t4[2]; bh[nt * 2 + 1][1] = t4[3];
                ldsm4(t4, st + B_OFF + row * 128 + (((cuB + kk * 2 + 4) ^ (row & 7)) << 4));
                bl[nt * 2][0] = t4[0]; bl[nt * 2][1] = t4[1];
                bl[nt * 2 + 1][0] = t4[2]; bl[nt * 2 + 1][1] = t4[3];
            }
#pragma unroll
            for (int mt = 0; mt < 2; mt++)
#pragma unroll
                for (int f = 0; f < 8; f++) {
                    mma_bf16(c[mt][f], ah[mt], bh[f]);
                    mma_bf16(c[mt][f], ah[mt], bl[f]);
                    mma_bf16(c[mt][f], al[mt], bh[f]);
                }
        }

        if (ch + 1 < nc) {
            char* stw = smc + ((ch + 1) & 1) * STAGE_BYTES;
#pragma unroll
            for (int j = 0; j < 4; j++) {
                uint2 hi, lo;
                hi.x = __byte_perm(va[j].x, va[j].y, 0x7632);
                lo.x = __byte_perm(va[j].x, va[j].y, 0x5410);
                hi.y = __byte_perm(va[j].z, va[j].w, 0x7632);
                lo.y = __byte_perm(va[j].z, va[j].w, 0x5410);
                *(uint2*)(stw + sh[j]) = hi;
                *(uint2*)(stw + sl[j]) = lo;
                hi.x = __byte_perm(vw[j].x, vw[j].y, 0x7632);
                lo.x = __byte_perm(vw[j].x, vw[j].y, 0x5410);
                hi.y = __byte_perm(vw[j].z, vw[j].w, 0x7632);
                lo.y = __byte_perm(vw[j].z, vw[j].w, 0x5410);
                *(uint2*)(stw + B_OFF + sh[j]) = hi;
                *(uint2*)(stw + B_OFF + sl[j]) = lo;
            }
            __syncthreads();
        }
    }

    // epilogue: bias + activation straight from fragments
#pragma unroll
    for (int mt = 0; mt < 2; mt++) {
        int row = m0 + wm + mt * 16 + (lane >> 2);
#pragma unroll
        for (int f = 0; f < 8; f++) {
            int col = n0 + wn + f * 8 + (lane & 3) * 2;
            float b0 = __ldg(&bias[col]), b1 = __ldg(&bias[col + 1]);
            float v0 = c[mt][f][0] + b0, v1 = c[mt][f][1] + b1;
            float v2 = c[mt][f][2] + b0, v3 = c[mt][f][3] + b1;
            if (act == 1) {
                v0 = tanhf(v0); v1 = tanhf(v1); v2 = tanhf(v2); v3 = tanhf(v3);
            } else if (act == 2) {
                v0 = fmaxf(v0, 0.f); v1 = fmaxf(v1, 0.f);
                v2 = fmaxf(v2, 0.f); v3 = fmaxf(v3, 0.f);
            }
            if (outpk) {
                uint32_t* Cp = (uint32_t*)Cv;
                uint2 p01; p01.x = pk(v0); p01.y = pk(v1);
                uint2 p23; p23.x = pk(v2); p23.y = pk(v3);
                *(uint2*)&Cp[(size_t)row * N + col] = p01;
                *(uint2*)&Cp[(size_t)(row + 8) * N + col] = p23;
            } else {
                float* Cf = (float*)Cv;
                *(float2*)&Cf[(size_t)row * N + col] = make_float2(v0, v1);
                *(float2*)&Cf[(size_t)(row + 8) * N + col] = make_float2(v2, v3);
            }
        }
    }
}

// ---------------- recurrence -----------------------------------------------
__device__ __forceinline__ float sigmoidf_(float x) {
    return 1.f / (1.f + expf(-x));
}

__device__ __forceinline__ void grid_barrier(unsigned* s_gen_p) {
    __syncthreads();
    if (threadIdx.x == 0) {
        unsigned my = *s_gen_p;
        __threadfence();
        unsigned t = atomicAdd(&g_bar_in, 1u);
        if (t == NCTA - 1) {
            g_bar_in = 0;
            __threadfence();
            atomicAdd(&g_bar_gen, 1u);
        } else {
            while (*(volatile unsigned*)&g_bar_gen == my) { }
        }
        *s_gen_p = my + 1;
    }
    __syncthreads();
}

__global__ void __launch_bounds__(256, 1) recur_kernel()
{
    __shared__ float hx_sm[8 * 256];
    __shared__ float red[2 * 128 * 9];
    __shared__ unsigned s_gen;

    int tid = threadIdx.x;
    int cta = blockIdx.x;
    int bs = cta >> 3, cs = cta & 7;

    // GEMM role: register-resident Wh row-half as packed f32 pairs
    int r  = tid & 127;
    int kh = tid >> 7;
    int gg = r >> 5, jl = r & 31;
    int R = gg * H_ + cs * 32 + jl;
    unsigned long long wreg2[64];
    {
        const ulonglong2* wp = (const ulonglong2*)&g_Wh[(size_t)R * H_ + kh * 128];
#pragma unroll
        for (int q = 0; q < 32; q++) {
            ulonglong2 v = wp[q];
            wreg2[2 * q] = v.x; wreg2[2 * q + 1] = v.y;
        }
    }

    int b    = tid >> 5;
    int lane = tid & 31;
    int bidx = bs * 8 + b;
    int col  = cs * 32 + lane;
    float cx = 0.f;

    g_hx[bidx * H_ + col] = 0.f;
    if (tid == 0) s_gen = *(volatile unsigned*)&g_bar_gen;
    grid_barrier(&s_gen);

    for (int t = 0; t < T_; t++) {
        int cur = t & 1, nxt = cur ^ 1;

        const float* gxrow = &g_gx[((size_t)t * B_ + bidx) * G4_ + col];
        float gx0 = __ldg(&gxrow[0]);
        float gx1 = __ldg(&gxrow[256]);
        float gx2 = __ldg(&gxrow[512]);
        float gx3 = __ldg(&gxrow[768]);

        {
            const float4* src = (const float4*)&g_hx[cur * (B_ * H_) + bs * 8 * H_];
            float4* dst = (float4*)hx_sm;
            dst[tid]       = __ldcg(&src[tid]);
            dst[tid + 256] = __ldcg(&src[tid + 256]);
        }
        __syncthreads();

        // hx @ Wh^T partial via packed dual-FMA (k-split accumulators)
        unsigned long long acc2[8];
#pragma unroll
        for (int bb = 0; bb < 8; bb++) acc2[bb] = 0ULL;
        const ulonglong2* hb2 = (const ulonglong2*)(hx_sm + kh * 128);
#pragma unroll
        for (int qq = 0; qq < 32; qq++) {
#pragma unroll
            for (int bb = 0; bb < 8; bb++) {
                ulonglong2 hv = hb2[bb * 64 + qq];
                fma2(acc2[bb], wreg2[2 * qq],     hv.x);
                fma2(acc2[bb], wreg2[2 * qq + 1], hv.y);
            }
        }
#pragma unroll
        for (int bb = 0; bb < 8; bb++) {
            unsigned long long a = acc2[bb];
            float alo = __uint_as_float((uint32_t)a);
            float ahi = __uint_as_float((uint32_t)(a >> 32));
            red[(kh * 128 + r) * 9 + bb] = alo + ahi;
        }
        __syncthreads();

        float s0 = red[(0 * 32 + lane) * 9 + b] + red[(128 + 0 * 32 + lane) * 9 + b];
        float s1 = red[(1 * 32 + lane) * 9 + b] + red[(128 + 1 * 32 + lane) * 9 + b];
        float s2 = red[(2 * 32 + lane) * 9 + b] + red[(128 + 2 * 32 + lane) * 9 + b];
        float s3 = red[(3 * 32 + lane) * 9 + b] + red[(128 + 3 * 32 + lane) * 9 + b];

        float fg = sigmoidf_(s0 + gx0);
        float ig = sigmoidf_(s1 + gx1);
        float ug = tanhf(s2 + gx2);
        float og = sigmoidf_(s3 + gx3);
        cx = fg * cx + ig * ug;
        float h = og * tanhf(cx);

        g_hx[nxt * (B_ * H_) + bidx * H_ + col] = h;
        g_hsb[((size_t)t * B_ + bidx) * H_ + col] = pk(h);

        grid_barrier(&s_gen);
    }
}

// ---------------- final tiny projection to 2 logits ------------------------
__global__ void __launch_bounds__(256) final_kernel(
    const float* __restrict__ z, const float* __restrict__ w2,
    const float* __restrict__ b2, float* __restrict__ out)
{
    __shared__ float w[512];
    __shared__ float bb[2];
    int tid = threadIdx.x;
    w[tid] = w2[tid];
    w[tid + 256] = w2[tid + 256];
    if (tid < 2) bb[tid] = b2[tid];
    __syncthreads();

    int row = blockIdx.x * 256 + tid;
    const float4* zp = (const float4*)&z[(size_t)row * H_];
    float a0 = 0.f, a1 = 0.f;
#pragma unroll
    for (int q = 0; q < 64; q++) {
        float4 v = zp[q];
        a0 = fmaf(v.x, w[4 * q + 0], a0);
        a0 = fmaf(v.y, w[4 * q + 1], a0);
        a0 = fmaf(v.z, w[4 * q + 2], a0);
        a0 = fmaf(v.w, w[4 * q + 3], a0);
        a1 = fmaf(v.x, w[256 + 4 * q + 0], a1);
        a1 = fmaf(v.y, w[256 + 4 * q + 1], a1);
        a1 = fmaf(v.z, w[256 + 4 * q + 2], a1);
        a1 = fmaf(v.w, w[256 + 4 * q + 3], a1);
    }
    out[row * 2 + 0] = a0 + bb[0];
    out[row * 2 + 1] = a1 + bb[1];
}

// ---------------- host -----------------------------------------------------
extern "C" void kernel_launch(void* const* d_in, const int* in_sizes, int n_in,
                              void* d_out, int out_size)
{
    const float* x    = (const float*)d_in[0];
    const float* fc_w = (const float*)d_in[1];
    const float* fc_b = (const float*)d_in[2];
    const float* fw   = (const float*)d_in[3];
    const float* fb   = (const float*)d_in[4];
    const float* iw   = (const float*)d_in[5];
    const float* ib   = (const float*)d_in[6];
    const float* uw   = (const float*)d_in[7];
    const float* ub   = (const float*)d_in[8];
    const float* ow   = (const float*)d_in[9];
    const float* ob   = (const float*)d_in[10];
    const float* w0   = (const float*)d_in[11];
    const float* b0   = (const float*)d_in[12];
    const float* w1   = (const float*)d_in[13];
    const float* b1   = (const float*)d_in[14];
    const float* w2   = (const float*)d_in[15];
    const float* b2   = (const float*)d_in[16];
    float* out = (float*)d_out;

    void *p_xp, *p_hb, *p_gx, *p_hsb, *p_z0b, *p_z1;
    void *p_wxp, *p_bias, *p_fcwp, *p_w0p, *p_w1p;
    cudaGetSymbolAddress(&p_xp,   g_xp);
    cudaGetSymbolAddress(&p_hb,   g_hb);
    cudaGetSymbolAddress(&p_gx,   g_gx);
    cudaGetSymbolAddress(&p_hsb,  g_hsb);
    cudaGetSymbolAddress(&p_z0b,  g_z0b);
    cudaGetSymbolAddress(&p_z1,   g_z1);
    cudaGetSymbolAddress(&p_wxp,  g_Wxp);
    cudaGetSymbolAddress(&p_bias, g_bias);
    cudaGetSymbolAddress(&p_fcwp, g_fcwp);
    cudaGetSymbolAddress(&p_w0p,  g_w0p);
    cudaGetSymbolAddress(&p_w1p,  g_w1p);

    cudaFuncSetAttribute(gemm_mma, cudaFuncAttributeMaxDynamicSharedMemorySize,
                         2 * STAGE_BYTES);

    // split-pack operands
    splitpack_kernel<<<(TB_ * D_ / 4) / 256, 256>>>(x, (uint32_t*)p_xp, TB_ * D_ / 4);
    splitpack_kernel<<<(H_ * D_ / 4) / 256, 256>>>(fc_w, (uint32_t*)p_fcwp, H_ * D_ / 4);
    splitpack_kernel<<<(H_ * H_ / 4) / 256, 256>>>(w0, (uint32_t*)p_w0p, H_ * H_ / 4);
    splitpack_kernel<<<(H_ * H_ / 4) / 256, 256>>>(w1, (uint32_t*)p_w1p, H_ * H_ / 4);
    pack_kernel<<<(G4_ * H_) / 256, 256>>>(fw, iw, uw, ow, fb, ib, ub, ob);

    // h = tanh(x @ fc_w^T + fc_b)   [TB,512] -> [TB,256] packed
    gemm_mma<<<dim3(H_ / 128, TB_ / 128), 256, 2 * STAGE_BYTES>>>(
        (const uint32_t*)p_xp, (const uint32_t*)p_fcwp, fc_b, p_hb, D_, H_, 1, 1);

    // gx = h @ Wx^T + bias          [TB,256] -> [TB,1024] f32
    gemm_mma<<<dim3(G4_ / 128, TB_ / 128), 256, 2 * STAGE_BYTES>>>(
        (const uint32_t*)p_hb, (const uint32_t*)p_wxp, (const float*)p_bias,
        p_gx, H_, G4_, 0, 0);

    // LSTM recurrence (persistent, grid-barrier synchronized)
    recur_kernel<<<NCTA, 256>>>();

    // classifier
    gemm_mma<<<dim3(H_ / 128, TB_ / 128), 256, 2 * STAGE_BYTES>>>(
        (const uint32_t*)p_hsb, (const uint32_t*)p_w0p, b0, p_z0b, H_, H_, 2, 1);
    gemm_mma<<<dim3(H_ / 128, TB_ / 128), 256, 2 * STAGE_BYTES>>>(
        (const uint32_t*)p_z0b, (const uint32_t*)p_w1p, b1, p_z1, H_, H_, 2, 0);
    final_kernel<<<TB_ / 256, 256>>>((const float*)p_z1, w2, b2, out);
}